// round 11
// baseline (speedup 1.0000x reference)
#include <cuda_runtime.h>
#include <cuda_bf16.h>

#define NN 100000
#define NE 1600000
#define DD 128
#define NSCAN 98  // ceil(NN/1024)

// ---------------- scratch (device globals; no allocation allowed) ----------
__device__ int g_deg[NN];          // zero at load (BSS); re-zeroed at end of gemm
__device__ int g_rowptr[NN];
__device__ int g_cursor[NN];
__device__ unsigned g_sflag[128];  // lookback scan: 0x80000000 | block_total
__device__ __align__(16) uint2 g_rec[NE];                      // packed {src,e,w}
__device__ __align__(16) __nv_bfloat16 g_Wh[128 * 256];        // W split hi, [c][k]
__device__ __align__(16) __nv_bfloat16 g_Wl[128 * 256];        // W split lo
__device__ __align__(16) __nv_bfloat16 g_Xh[(size_t)NN * 256]; // X split hi, [n][k]
__device__ __align__(16) __nv_bfloat16 g_Xl[(size_t)NN * 256]; // X split lo

// ---------------- helpers ---------------------------------------------------
__device__ __forceinline__ unsigned pack_bf2(__nv_bfloat16 a, __nv_bfloat16 b) {
    return ((unsigned)__bfloat16_as_ushort(b) << 16) | (unsigned)__bfloat16_as_ushort(a);
}

__device__ __forceinline__ void mma_bf16(float* c, unsigned a0, unsigned a1, unsigned a2,
                                         unsigned a3, unsigned b0, unsigned b1) {
    asm volatile(
        "mma.sync.aligned.m16n8k16.row.col.f32.bf16.bf16.f32 "
        "{%0,%1,%2,%3}, {%4,%5,%6,%7}, {%8,%9}, {%0,%1,%2,%3};"
        : "+f"(c[0]), "+f"(c[1]), "+f"(c[2]), "+f"(c[3])
        : "r"(a0), "r"(a1), "r"(a2), "r"(a3), "r"(b0), "r"(b1));
}

__device__ __forceinline__ void cp16(void* dst_smem, const void* src, bool pred) {
    unsigned d = (unsigned)__cvta_generic_to_shared(dst_smem);
    int sz = pred ? 16 : 0;
    asm volatile("cp.async.cg.shared.global [%0], [%1], 16, %2;\n"
                 :: "r"(d), "l"(src), "r"(sz));
}
__device__ __forceinline__ void cp_commit() {
    asm volatile("cp.async.commit_group;\n" ::: "memory");
}
template <int N>
__device__ __forceinline__ void cp_wait() {
    asm volatile("cp.async.wait_group %0;\n" :: "n"(N) : "memory");
}

// rec pack: w0 = src(17b) | (e&0x7FFF)<<17 ; w1 = (e>>15)(6b) | wbits&~0x3F
__device__ __forceinline__ uint2 rec_pack(int src, int e, float w) {
    unsigned wb = __float_as_uint(w);
    return make_uint2((unsigned)src | ((unsigned)(e & 0x7FFF) << 17),
                      (wb & 0xFFFFFFC0u) | (unsigned)(e >> 15));
}

// ---------------- K0 (launch 0): deg histogram + W split + flag clear -------
__global__ void k_deg(const int* __restrict__ dst, const float* __restrict__ Wn,
                      const float* __restrict__ We) {
    int gid = blockIdx.x * blockDim.x + threadIdx.x;
    int stride = gridDim.x * blockDim.x;
    for (int j = gid; j < NSCAN; j += stride) g_sflag[j] = 0;
    for (int j = gid; j < 128 * 256; j += stride) {
        int c = j >> 8, k = j & 255;
        float w = (k < 128) ? Wn[c * 128 + k] : We[c * 128 + (k - 128)];
        __nv_bfloat16 hi = __float2bfloat16_rn(w);
        __nv_bfloat16 lo = __float2bfloat16_rn(w - __bfloat162float(hi));
        g_Wh[j] = hi;
        g_Wl[j] = lo;
    }
    const int4* dst4 = (const int4*)dst;
    for (int i = gid; i < NE / 4; i += stride) {
        int4 d = __ldg(&dst4[i]);
        atomicAdd(&g_deg[d.x], 1);
        atomicAdd(&g_deg[d.y], 1);
        atomicAdd(&g_deg[d.z], 1);
        atomicAdd(&g_deg[d.w], 1);
    }
}

// ---------------- K1 (launch 1): fused scan, decoupled lookback -------------
// 98 CTAs <= 148 SMs: all resident in wave 1, so every predecessor publishes.
__global__ void __launch_bounds__(1024) k_scan() {
    __shared__ int sh[1024];
    __shared__ int s_prefix;
    int gid = blockIdx.x * 1024 + threadIdx.x;
    int v = (gid < NN) ? g_deg[gid] : 0;
    sh[threadIdx.x] = v;
    __syncthreads();
    for (int off = 1; off < 1024; off <<= 1) {
        int t = (threadIdx.x >= (unsigned)off) ? sh[threadIdx.x - off] : 0;
        __syncthreads();
        sh[threadIdx.x] += t;
        __syncthreads();
    }
    // publish this block's total (single tagged word -> no flag/data hazard)
    if (threadIdx.x == 1023) {
        __threadfence();
        ((volatile unsigned*)g_sflag)[blockIdx.x] = 0x80000000u | (unsigned)sh[1023];
    }
    // lookback: warp 0 sums all predecessor totals
    if (threadIdx.x < 32) {
        int acc = 0;
        for (int p = threadIdx.x; p < (int)blockIdx.x; p += 32) {
            unsigned f;
            while (!((f = ((volatile unsigned*)g_sflag)[p]) & 0x80000000u))
                __nanosleep(100);
            acc += (int)(f & 0x7FFFFFFFu);
        }
#pragma unroll
        for (int o = 16; o; o >>= 1) acc += __shfl_xor_sync(0xffffffffu, acc, o);
        if (threadIdx.x == 0) s_prefix = acc;
    }
    __syncthreads();
    if (gid < NN) {
        int r = sh[threadIdx.x] - v + s_prefix;  // exclusive global
        g_rowptr[gid] = r;
        g_cursor[gid] = r;
    }
}

// ---------------- K2 (launch 2): fill CSR, packed 8B records ----------------
__global__ void k_fill(const int* __restrict__ dst, const int* __restrict__ src,
                       const float* __restrict__ ew) {
    int gid = blockIdx.x * blockDim.x + threadIdx.x;
    int stride = gridDim.x * blockDim.x;
    const int4* dst4 = (const int4*)dst;
    const int4* src4 = (const int4*)src;
    const float4* ew4 = (const float4*)ew;
    for (int i = gid; i < NE / 4; i += stride) {
        int4 d = __ldg(&dst4[i]);
        int4 s = __ldg(&src4[i]);
        float4 w = __ldg(&ew4[i]);
        int e = i * 4;
        __stcs(&g_rec[atomicAdd(&g_cursor[d.x], 1)], rec_pack(s.x, e + 0, w.x));
        __stcs(&g_rec[atomicAdd(&g_cursor[d.y], 1)], rec_pack(s.y, e + 1, w.y));
        __stcs(&g_rec[atomicAdd(&g_cursor[d.z], 1)], rec_pack(s.z, e + 2, w.z));
        __stcs(&g_rec[atomicAdd(&g_cursor[d.w], 1)], rec_pack(s.w, e + 3, w.w));
    }
}

// ---------------- K3 (launch 3, ncu-profiled slot): gather aggregation ------
__global__ void __launch_bounds__(256) k_agg(const float* __restrict__ nfeat,
                                             const float* __restrict__ efeat) {
    int n = (blockIdx.x * 256 + threadIdx.x) >> 5;
    if (n >= NN) return;
    int lane = threadIdx.x & 31;
    int c = lane * 4;

    int start = g_rowptr[n];
    int cnt = g_deg[n];

    float4 sf = *(const float4*)&nfeat[(size_t)n * DD + c];
    float an0 = 2.f * sf.x, an1 = 2.f * sf.y, an2 = 2.f * sf.z, an3 = 2.f * sf.w;
    float ae0 = 0.f, ae1 = 0.f, ae2 = 0.f, ae3 = 0.f;

    int i = 0;
    if (cnt >= 4) {
        uint2 q0 = __ldcs(&g_rec[start + 0]);
        uint2 q1 = __ldcs(&g_rec[start + 1]);
        uint2 q2 = __ldcs(&g_rec[start + 2]);
        uint2 q3 = __ldcs(&g_rec[start + 3]);
        for (; i + 4 <= cnt;) {
            int s0 = q0.x & 0x1FFFF, s1 = q1.x & 0x1FFFF;
            int s2 = q2.x & 0x1FFFF, s3 = q3.x & 0x1FFFF;
            int e0 = (q0.x >> 17) | ((q0.y & 0x3F) << 15);
            int e1 = (q1.x >> 17) | ((q1.y & 0x3F) << 15);
            int e2 = (q2.x >> 17) | ((q2.y & 0x3F) << 15);
            int e3 = (q3.x >> 17) | ((q3.y & 0x3F) << 15);
            float w0 = __uint_as_float(q0.y & 0xFFFFFFC0u);
            float w1 = __uint_as_float(q1.y & 0xFFFFFFC0u);
            float w2 = __uint_as_float(q2.y & 0xFFFFFFC0u);
            float w3 = __uint_as_float(q3.y & 0xFFFFFFC0u);

            float4 v0 = __ldg((const float4*)&nfeat[(size_t)s0 * DD + c]);
            float4 v1 = __ldg((const float4*)&nfeat[(size_t)s1 * DD + c]);
            float4 v2 = __ldg((const float4*)&nfeat[(size_t)s2 * DD + c]);
            float4 v3 = __ldg((const float4*)&nfeat[(size_t)s3 * DD + c]);
            float4 u0 = __ldcs((const float4*)&efeat[(size_t)e0 * DD + c]);
            float4 u1 = __ldcs((const float4*)&efeat[(size_t)e1 * DD + c]);
            float4 u2 = __ldcs((const float4*)&efeat[(size_t)e2 * DD + c]);
            float4 u3 = __ldcs((const float4*)&efeat[(size_t)e3 * DD + c]);

            // prefetch next 4 records while feature loads are in flight
            int nx = i + 4;
            uint2 p0 = q0, p1 = q1, p2 = q2, p3 = q3;
            if (nx + 4 <= cnt) {
                p0 = __ldcs(&g_rec[start + nx + 0]);
                p1 = __ldcs(&g_rec[start + nx + 1]);
                p2 = __ldcs(&g_rec[start + nx + 2]);
                p3 = __ldcs(&g_rec[start + nx + 3]);
            }

            an0 += v0.x * w0 + v1.x * w1 + v2.x * w2 + v3.x * w3;
            an1 += v0.y * w0 + v1.y * w1 + v2.y * w2 + v3.y * w3;
            an2 += v0.z * w0 + v1.z * w1 + v2.z * w2 + v3.z * w3;
            an3 += v0.w * w0 + v1.w * w1 + v2.w * w2 + v3.w * w3;
            ae0 += (u0.x + u1.x) + (u2.x + u3.x);
            ae1 += (u0.y + u1.y) + (u2.y + u3.y);
            ae2 += (u0.z + u1.z) + (u2.z + u3.z);
            ae3 += (u0.w + u1.w) + (u2.w + u3.w);

            q0 = p0; q1 = p1; q2 = p2; q3 = p3;
            i = nx;
        }
    }
    for (; i < cnt; i++) {
        uint2 q0 = __ldcs(&g_rec[start + i]);
        int s0 = q0.x & 0x1FFFF;
        int e0 = (q0.x >> 17) | ((q0.y & 0x3F) << 15);
        float w0 = __uint_as_float(q0.y & 0xFFFFFFC0u);
        float4 v0 = __ldg((const float4*)&nfeat[(size_t)s0 * DD + c]);
        float4 u0 = __ldcs((const float4*)&efeat[(size_t)e0 * DD + c]);
        an0 += v0.x * w0; an1 += v0.y * w0; an2 += v0.z * w0; an3 += v0.w * w0;
        ae0 += u0.x; ae1 += u0.y; ae2 += u0.z; ae3 += u0.w;
    }

    float invd = 1.f / (float)(cnt + 1);
    float inve = (cnt > 0) ? 1.f / (float)cnt : 0.f;
    float xv[8] = {an0 * invd, an1 * invd, an2 * invd, an3 * invd,
                   ae0 * inve, ae1 * inve, ae2 * inve, ae3 * inve};

    unsigned hp[4], lp[4];
#pragma unroll
    for (int p = 0; p < 4; p++) {
        __nv_bfloat16 h0 = __float2bfloat16_rn(xv[2 * p]);
        __nv_bfloat16 h1 = __float2bfloat16_rn(xv[2 * p + 1]);
        __nv_bfloat16 l0 = __float2bfloat16_rn(xv[2 * p] - __bfloat162float(h0));
        __nv_bfloat16 l1 = __float2bfloat16_rn(xv[2 * p + 1] - __bfloat162float(h1));
        hp[p] = pack_bf2(h0, h1);
        lp[p] = pack_bf2(l0, l1);
    }
    size_t base = (size_t)n * 256 + c;
    *(uint2*)&g_Xh[base]       = make_uint2(hp[0], hp[1]);
    *(uint2*)&g_Xh[base + 128] = make_uint2(hp[2], hp[3]);
    *(uint2*)&g_Xl[base]       = make_uint2(lp[0], lp[1]);
    *(uint2*)&g_Xl[base + 128] = make_uint2(lp[2], lp[3]);
}

// ---------------- K4: tensor-core GEMM, bf16x3 split, cp.async 2-stage ------
// out = Xh*Wh + Xh*Wl + Xl*Wh + bias; also re-zeroes g_deg for next replay.
#define GPITCH 40
#define GSTAGE 20480
#define GARR   5120

__global__ void __launch_bounds__(256, 2) k_gemm_tc(const float* __restrict__ bn,
                                                    const float* __restrict__ be,
                                                    float* __restrict__ out) {
    extern __shared__ __nv_bfloat16 smem[];
    int tid = threadIdx.x;
    int lane = tid & 31, wid = tid >> 5;
    int g = lane >> 2, t = lane & 3;
    int mw = (wid >> 1) * 32, nw = (wid & 1) * 64;
    int rowbase = blockIdx.x * 128;

    float acc[2][8][4];
#pragma unroll
    for (int mt = 0; mt < 2; mt++)
#pragma unroll
        for (int nt = 0; nt < 8; nt++)
#pragma unroll
            for (int p = 0; p < 4; p++) acc[mt][nt][p] = 0.f;

    auto issue = [&](int kc, int s) {
        __nv_bfloat16* Sxh = smem + s * GSTAGE;
        __nv_bfloat16* Sxl = Sxh + GARR;
        __nv_bfloat16* Swh = Sxl + GARR;
        __nv_bfloat16* Swl = Swh + GARR;
#pragma unroll
        for (int tt = 0; tt < 2; tt++) {
            int cc = tid + tt * 256;
            int row = cc >> 2, c16 = cc & 3;
            size_t gx = (size_t)(rowbase + row) * 256 + kc + c16 * 8;
            bool inb = (rowbase + row) < NN;
            cp16(&Sxh[row * GPITCH + c16 * 8], &g_Xh[gx], inb);
            cp16(&Sxl[row * GPITCH + c16 * 8], &g_Xl[gx], inb);
            size_t gw = (size_t)row * 256 + kc + c16 * 8;
            cp16(&Swh[row * GPITCH + c16 * 8], &g_Wh[gw], true);
            cp16(&Swl[row * GPITCH + c16 * 8], &g_Wl[gw], true);
        }
    };

    issue(0, 0);
    cp_commit();

    for (int it = 0; it < 8; it++) {
        if (it < 7) {
            issue((it + 1) * 32, (it + 1) & 1);
            cp_commit();
            cp_wait<1>();
        } else {
            cp_wait<0>();
        }
        __syncthreads();

        const __nv_bfloat16* Sxh = smem + (it & 1) * GSTAGE;
        const __nv_bfloat16* Sxl = Sxh + GARR;
        const __nv_bfloat16* Swh = Sxl + GARR;
        const __nv_bfloat16* Swl = Swh + GARR;

#pragma unroll
        for (int kk = 0; kk < 32; kk += 16) {
            unsigned ah[2][4], al[2][4];
#pragma unroll
            for (int mt = 0; mt < 2; mt++) {
                int rb = mw + mt * 16;
                ah[mt][0] = *(const unsigned*)&Sxh[(rb + g) * GPITCH + kk + t * 2];
                ah[mt][1] = *(const unsigned*)&Sxh[(rb + g + 8) * GPITCH + kk + t * 2];
                ah[mt][2] = *(const unsigned*)&Sxh[(rb + g) * GPITCH + kk + t * 2 + 8];
                ah[mt][3] = *(const unsigned*)&Sxh[(rb + g + 8) * GPITCH + kk + t * 2 + 8];
                al[mt][0] = *(const unsigned*)&Sxl[(rb + g) * GPITCH + kk + t * 2];
                al[mt][1] = *(const unsigned*)&Sxl[(rb + g + 8) * GPITCH + kk + t * 2];
                al[mt][2] = *(const unsigned*)&Sxl[(rb + g) * GPITCH + kk + t * 2 + 8];
                al[mt][3] = *(const unsigned*)&Sxl[(rb + g + 8) * GPITCH + kk + t * 2 + 8];
            }
#pragma unroll
            for (int nt = 0; nt < 8; nt++) {
                int nb = nw + nt * 8;
                unsigned bh0 = *(const unsigned*)&Swh[(nb + g) * GPITCH + kk + t * 2];
                unsigned bh1 = *(const unsigned*)&Swh[(nb + g) * GPITCH + kk + t * 2 + 8];
                unsigned bl0 = *(const unsigned*)&Swl[(nb + g) * GPITCH + kk + t * 2];
                unsigned bl1 = *(const unsigned*)&Swl[(nb + g) * GPITCH + kk + t * 2 + 8];
#pragma unroll
                for (int mt = 0; mt < 2; mt++) {
                    mma_bf16(acc[mt][nt], ah[mt][0], ah[mt][1], ah[mt][2], ah[mt][3], bh0, bh1);
                    mma_bf16(acc[mt][nt], ah[mt][0], ah[mt][1], ah[mt][2], ah[mt][3], bl0, bl1);
                    mma_bf16(acc[mt][nt], al[mt][0], al[mt][1], al[mt][2], al[mt][3], bh0, bh1);
                }
            }
        }
        __syncthreads();
    }

    // epilogue: bias + deg-gated edge bias
#pragma unroll
    for (int nt = 0; nt < 8; nt++) {
        int col = nw + nt * 8 + t * 2;
        float bn0 = __ldg(&bn[col]), bn1 = __ldg(&bn[col + 1]);
        float be0 = __ldg(&be[col]), be1 = __ldg(&be[col + 1]);
#pragma unroll
        for (int mt = 0; mt < 2; mt++) {
            int m0 = rowbase + mw + mt * 16 + g;
            if (m0 < NN) {
                float f = (g_deg[m0] > 0) ? 1.f : 0.f;
                __stcs((float2*)&out[(size_t)m0 * DD + col],
                       make_float2(acc[mt][nt][0] + bn0 + f * be0,
                                   acc[mt][nt][1] + bn1 + f * be1));
            }
            int m1 = m0 + 8;
            if (m1 < NN) {
                float f = (g_deg[m1] > 0) ? 1.f : 0.f;
                __stcs((float2*)&out[(size_t)m1 * DD + col],
                       make_float2(acc[mt][nt][2] + bn0 + f * be0,
                                   acc[mt][nt][3] + bn1 + f * be1));
            }
        }
    }

    // re-zero this CTA's g_deg rows for the next graph replay
    __syncthreads();
    if (tid < 128) {
        int m = rowbase + tid;
        if (m < NN) g_deg[m] = 0;
    }
}

// ---------------- launch ----------------------------------------------------
extern "C" void kernel_launch(void* const* d_in, const int* in_sizes, int n_in,
                              void* d_out, int out_size) {
    const float* nfeat = (const float*)d_in[0];
    const float* efeat = (const float*)d_in[1];
    const float* ew    = (const float*)d_in[2];
    const float* Wn    = (const float*)d_in[3];
    const float* bn    = (const float*)d_in[4];
    const float* We    = (const float*)d_in[5];
    const float* be    = (const float*)d_in[6];
    const int*   src   = (const int*)d_in[7];
    const int*   dst   = (const int*)d_in[8];
    float* out = (float*)d_out;

    const int gemm_smem = 2 * 4 * 128 * GPITCH * (int)sizeof(__nv_bfloat16);  // 81920
    cudaFuncSetAttribute(k_gemm_tc, cudaFuncAttributeMaxDynamicSharedMemorySize, gemm_smem);

    k_deg<<<800, 256>>>(dst, Wn, We);                       // #0: deg + Wsplit + flags
    k_scan<<<NSCAN, 1024>>>();                              // #1: fused lookback scan
    k_fill<<<(NE / 4 + 255) / 256, 256>>>(dst, src, ew);    // #2: packed CSR fill
    k_agg<<<(NN * 32 + 255) / 256, 256>>>(nfeat, efeat);    // #3: (profiled slot)
    k_gemm_tc<<<(NN + 127) / 128, 256, gemm_smem>>>(bn, be, out);  // #4
}

// round 16
// speedup vs baseline: 1.2457x; 1.2457x over previous
#include <cuda_runtime.h>
#include <cuda_bf16.h>

#define NN 100000
#define NE 1600000
#define DD 128
#define NSCAN 98  // ceil(NN/1024)

// ---------------- scratch (device globals; no allocation allowed) ----------
__device__ int g_deg[NN];          // zero at load (BSS); re-zeroed at end of gemm
__device__ int g_rowptr[NN];
__device__ int g_cursor[NN];
__device__ unsigned g_sflag[128];  // lookback scan: 0x80000000 | block_total
__device__ __align__(16) uint2 g_rec[NE];                      // packed {src,e,w}
__device__ __align__(16) __nv_bfloat16 g_Wh[128 * 256];        // W split hi, [c][k]
__device__ __align__(16) __nv_bfloat16 g_Wl[128 * 256];        // W split lo
__device__ __align__(16) __nv_bfloat16 g_Xh[(size_t)NN * 256]; // X split hi, [n][k]
__device__ __align__(16) __nv_bfloat16 g_Xl[(size_t)NN * 256]; // X split lo

// ---------------- helpers ---------------------------------------------------
__device__ __forceinline__ unsigned pack_bf2(__nv_bfloat16 a, __nv_bfloat16 b) {
    return ((unsigned)__bfloat16_as_ushort(b) << 16) | (unsigned)__bfloat16_as_ushort(a);
}

__device__ __forceinline__ void mma_bf16(float* c, unsigned a0, unsigned a1, unsigned a2,
                                         unsigned a3, unsigned b0, unsigned b1) {
    asm volatile(
        "mma.sync.aligned.m16n8k16.row.col.f32.bf16.bf16.f32 "
        "{%0,%1,%2,%3}, {%4,%5,%6,%7}, {%8,%9}, {%0,%1,%2,%3};"
        : "+f"(c[0]), "+f"(c[1]), "+f"(c[2]), "+f"(c[3])
        : "r"(a0), "r"(a1), "r"(a2), "r"(a3), "r"(b0), "r"(b1));
}

__device__ __forceinline__ void cp16(void* dst_smem, const void* src, bool pred) {
    unsigned d = (unsigned)__cvta_generic_to_shared(dst_smem);
    int sz = pred ? 16 : 0;
    asm volatile("cp.async.cg.shared.global [%0], [%1], 16, %2;\n"
                 :: "r"(d), "l"(src), "r"(sz));
}
__device__ __forceinline__ void cp_commit() {
    asm volatile("cp.async.commit_group;\n" ::: "memory");
}
template <int N>
__device__ __forceinline__ void cp_wait() {
    asm volatile("cp.async.wait_group %0;\n" :: "n"(N) : "memory");
}

__device__ __forceinline__ void pf_l2(const void* p) {
    asm volatile("prefetch.global.L2 [%0];" :: "l"(p));
}

// rec pack: w0 = src(17b) | (e&0x7FFF)<<17 ; w1 = (e>>15)(6b) | wbits&~0x3F
__device__ __forceinline__ uint2 rec_pack(int src, int e, float w) {
    unsigned wb = __float_as_uint(w);
    return make_uint2((unsigned)src | ((unsigned)(e & 0x7FFF) << 17),
                      (wb & 0xFFFFFFC0u) | (unsigned)(e >> 15));
}
__device__ __forceinline__ void rec_unpack(uint2 q, int& s, int& e, float& w) {
    s = q.x & 0x1FFFF;
    e = (q.x >> 17) | ((q.y & 0x3F) << 15);
    w = __uint_as_float(q.y & 0xFFFFFFC0u);
}

// ---------------- K0 (launch 0): deg histogram + W split + flag clear -------
__global__ void k_deg(const int* __restrict__ dst, const float* __restrict__ Wn,
                      const float* __restrict__ We) {
    int gid = blockIdx.x * blockDim.x + threadIdx.x;
    int stride = gridDim.x * blockDim.x;
    for (int j = gid; j < NSCAN; j += stride) g_sflag[j] = 0;
    for (int j = gid; j < 128 * 256; j += stride) {
        int c = j >> 8, k = j & 255;
        float w = (k < 128) ? Wn[c * 128 + k] : We[c * 128 + (k - 128)];
        __nv_bfloat16 hi = __float2bfloat16_rn(w);
        __nv_bfloat16 lo = __float2bfloat16_rn(w - __bfloat162float(hi));
        g_Wh[j] = hi;
        g_Wl[j] = lo;
    }
    const int4* dst4 = (const int4*)dst;
    for (int i = gid; i < NE / 4; i += stride) {
        int4 d = __ldg(&dst4[i]);
        atomicAdd(&g_deg[d.x], 1);
        atomicAdd(&g_deg[d.y], 1);
        atomicAdd(&g_deg[d.z], 1);
        atomicAdd(&g_deg[d.w], 1);
    }
}

// ---------------- K1 (launch 1): fused scan, decoupled lookback -------------
__global__ void __launch_bounds__(1024) k_scan() {
    __shared__ int sh[1024];
    __shared__ int s_prefix;
    int gid = blockIdx.x * 1024 + threadIdx.x;
    int v = (gid < NN) ? g_deg[gid] : 0;
    sh[threadIdx.x] = v;
    __syncthreads();
    for (int off = 1; off < 1024; off <<= 1) {
        int t = (threadIdx.x >= (unsigned)off) ? sh[threadIdx.x - off] : 0;
        __syncthreads();
        sh[threadIdx.x] += t;
        __syncthreads();
    }
    if (threadIdx.x == 1023) {
        __threadfence();
        ((volatile unsigned*)g_sflag)[blockIdx.x] = 0x80000000u | (unsigned)sh[1023];
    }
    if (threadIdx.x < 32) {
        int acc = 0;
        for (int p = threadIdx.x; p < (int)blockIdx.x; p += 32) {
            unsigned f;
            while (!((f = ((volatile unsigned*)g_sflag)[p]) & 0x80000000u))
                __nanosleep(100);
            acc += (int)(f & 0x7FFFFFFFu);
        }
#pragma unroll
        for (int o = 16; o; o >>= 1) acc += __shfl_xor_sync(0xffffffffu, acc, o);
        if (threadIdx.x == 0) s_prefix = acc;
    }
    __syncthreads();
    if (gid < NN) {
        int r = sh[threadIdx.x] - v + s_prefix;
        g_rowptr[gid] = r;
        g_cursor[gid] = r;
    }
}

// ---------------- K2 (launch 2): fill CSR, packed 8B records ----------------
// rec is 12.8 MB -> L2-resident; plain (evict-normal) stores, NOT streaming.
__global__ void k_fill(const int* __restrict__ dst, const int* __restrict__ src,
                       const float* __restrict__ ew) {
    int gid = blockIdx.x * blockDim.x + threadIdx.x;
    int stride = gridDim.x * blockDim.x;
    const int4* dst4 = (const int4*)dst;
    const int4* src4 = (const int4*)src;
    const float4* ew4 = (const float4*)ew;
    for (int i = gid; i < NE / 4; i += stride) {
        int4 d = __ldg(&dst4[i]);
        int4 s = __ldg(&src4[i]);
        float4 w = __ldg(&ew4[i]);
        int e = i * 4;
        g_rec[atomicAdd(&g_cursor[d.x], 1)] = rec_pack(s.x, e + 0, w.x);
        g_rec[atomicAdd(&g_cursor[d.y], 1)] = rec_pack(s.y, e + 1, w.y);
        g_rec[atomicAdd(&g_cursor[d.z], 1)] = rec_pack(s.z, e + 2, w.z);
        g_rec[atomicAdd(&g_cursor[d.w], 1)] = rec_pack(s.w, e + 3, w.w);
    }
}

// ---------------- K3 (launch 3, profiled slot): gather agg + L2 prefetch ----
__global__ void __launch_bounds__(256) k_agg(const float* __restrict__ nfeat,
                                             const float* __restrict__ efeat) {
    int n = (blockIdx.x * 256 + threadIdx.x) >> 5;
    if (n >= NN) return;
    int lane = threadIdx.x & 31;
    int c = lane * 4;

    int start = g_rowptr[n];
    int cnt = g_deg[n];

    float4 sf = *(const float4*)&nfeat[(size_t)n * DD + c];
    float an0 = 2.f * sf.x, an1 = 2.f * sf.y, an2 = 2.f * sf.z, an3 = 2.f * sf.w;
    float ae0 = 0.f, ae1 = 0.f, ae2 = 0.f, ae3 = 0.f;

    int i = 0;
    if (cnt >= 8) {
        uint2 q0 = __ldg(&g_rec[start + 0]);
        uint2 q1 = __ldg(&g_rec[start + 1]);
        uint2 q2 = __ldg(&g_rec[start + 2]);
        uint2 q3 = __ldg(&g_rec[start + 3]);
        uint2 p0 = __ldg(&g_rec[start + 4]);
        uint2 p1 = __ldg(&g_rec[start + 5]);
        uint2 p2 = __ldg(&g_rec[start + 6]);
        uint2 p3 = __ldg(&g_rec[start + 7]);
        while (i + 8 <= cnt) {
            // --- prefetch NEXT group's feature rows into L2 (1 iter of lead) ---
            int ps0, ps1, ps2, ps3, pe0, pe1, pe2, pe3;
            float pw;
            rec_unpack(p0, ps0, pe0, pw);
            rec_unpack(p1, ps1, pe1, pw);
            rec_unpack(p2, ps2, pe2, pw);
            rec_unpack(p3, ps3, pe3, pw);
            pf_l2(&nfeat[(size_t)ps0 * DD + c]);
            pf_l2(&nfeat[(size_t)ps1 * DD + c]);
            pf_l2(&nfeat[(size_t)ps2 * DD + c]);
            pf_l2(&nfeat[(size_t)ps3 * DD + c]);
            pf_l2(&efeat[(size_t)pe0 * DD + c]);
            pf_l2(&efeat[(size_t)pe1 * DD + c]);
            pf_l2(&efeat[(size_t)pe2 * DD + c]);
            pf_l2(&efeat[(size_t)pe3 * DD + c]);

            // --- demand loads for CURRENT group ---
            int s0, s1, s2, s3, e0, e1, e2, e3;
            float w0, w1, w2, w3;
            rec_unpack(q0, s0, e0, w0);
            rec_unpack(q1, s1, e1, w1);
            rec_unpack(q2, s2, e2, w2);
            rec_unpack(q3, s3, e3, w3);
            float4 v0 = __ldg((const float4*)&nfeat[(size_t)s0 * DD + c]);
            float4 v1 = __ldg((const float4*)&nfeat[(size_t)s1 * DD + c]);
            float4 v2 = __ldg((const float4*)&nfeat[(size_t)s2 * DD + c]);
            float4 v3 = __ldg((const float4*)&nfeat[(size_t)s3 * DD + c]);
            float4 u0 = __ldcs((const float4*)&efeat[(size_t)e0 * DD + c]);
            float4 u1 = __ldcs((const float4*)&efeat[(size_t)e1 * DD + c]);
            float4 u2 = __ldcs((const float4*)&efeat[(size_t)e2 * DD + c]);
            float4 u3 = __ldcs((const float4*)&efeat[(size_t)e3 * DD + c]);

            // --- load rec group i+8 (L2-hot) while features are in flight ---
            uint2 t0 = p0, t1 = p1, t2 = p2, t3 = p3;
            if (i + 12 <= cnt) {
                t0 = __ldg(&g_rec[start + i + 8]);
                t1 = __ldg(&g_rec[start + i + 9]);
                t2 = __ldg(&g_rec[start + i + 10]);
                t3 = __ldg(&g_rec[start + i + 11]);
            }

            an0 += v0.x * w0 + v1.x * w1 + v2.x * w2 + v3.x * w3;
            an1 += v0.y * w0 + v1.y * w1 + v2.y * w2 + v3.y * w3;
            an2 += v0.z * w0 + v1.z * w1 + v2.z * w2 + v3.z * w3;
            an3 += v0.w * w0 + v1.w * w1 + v2.w * w2 + v3.w * w3;
            ae0 += (u0.x + u1.x) + (u2.x + u3.x);
            ae1 += (u0.y + u1.y) + (u2.y + u3.y);
            ae2 += (u0.z + u1.z) + (u2.z + u3.z);
            ae3 += (u0.w + u1.w) + (u2.w + u3.w);

            q0 = p0; q1 = p1; q2 = p2; q3 = p3;
            p0 = t0; p1 = t1; p2 = t2; p3 = t3;
            i += 4;
        }
    }
    // drain: remaining < 8 edges (recs are L2-hot)
    for (; i + 4 <= cnt; i += 4) {
        uint2 r0 = __ldg(&g_rec[start + i]);
        uint2 r1 = __ldg(&g_rec[start + i + 1]);
        uint2 r2 = __ldg(&g_rec[start + i + 2]);
        uint2 r3 = __ldg(&g_rec[start + i + 3]);
        int s0, s1, s2, s3, e0, e1, e2, e3;
        float w0, w1, w2, w3;
        rec_unpack(r0, s0, e0, w0);
        rec_unpack(r1, s1, e1, w1);
        rec_unpack(r2, s2, e2, w2);
        rec_unpack(r3, s3, e3, w3);
        float4 v0 = __ldg((const float4*)&nfeat[(size_t)s0 * DD + c]);
        float4 v1 = __ldg((const float4*)&nfeat[(size_t)s1 * DD + c]);
        float4 v2 = __ldg((const float4*)&nfeat[(size_t)s2 * DD + c]);
        float4 v3 = __ldg((const float4*)&nfeat[(size_t)s3 * DD + c]);
        float4 u0 = __ldcs((const float4*)&efeat[(size_t)e0 * DD + c]);
        float4 u1 = __ldcs((const float4*)&efeat[(size_t)e1 * DD + c]);
        float4 u2 = __ldcs((const float4*)&efeat[(size_t)e2 * DD + c]);
        float4 u3 = __ldcs((const float4*)&efeat[(size_t)e3 * DD + c]);
        an0 += v0.x * w0 + v1.x * w1 + v2.x * w2 + v3.x * w3;
        an1 += v0.y * w0 + v1.y * w1 + v2.y * w2 + v3.y * w3;
        an2 += v0.z * w0 + v1.z * w1 + v2.z * w2 + v3.z * w3;
        an3 += v0.w * w0 + v1.w * w1 + v2.w * w2 + v3.w * w3;
        ae0 += (u0.x + u1.x) + (u2.x + u3.x);
        ae1 += (u0.y + u1.y) + (u2.y + u3.y);
        ae2 += (u0.z + u1.z) + (u2.z + u3.z);
        ae3 += (u0.w + u1.w) + (u2.w + u3.w);
    }
    for (; i < cnt; i++) {
        uint2 r0 = __ldg(&g_rec[start + i]);
        int s0, e0;
        float w0;
        rec_unpack(r0, s0, e0, w0);
        float4 v0 = __ldg((const float4*)&nfeat[(size_t)s0 * DD + c]);
        float4 u0 = __ldcs((const float4*)&efeat[(size_t)e0 * DD + c]);
        an0 += v0.x * w0; an1 += v0.y * w0; an2 += v0.z * w0; an3 += v0.w * w0;
        ae0 += u0.x; ae1 += u0.y; ae2 += u0.z; ae3 += u0.w;
    }

    float invd = 1.f / (float)(cnt + 1);
    float inve = (cnt > 0) ? 1.f / (float)cnt : 0.f;
    float xv[8] = {an0 * invd, an1 * invd, an2 * invd, an3 * invd,
                   ae0 * inve, ae1 * inve, ae2 * inve, ae3 * inve};

    unsigned hp[4], lp[4];
#pragma unroll
    for (int p = 0; p < 4; p++) {
        __nv_bfloat16 h0 = __float2bfloat16_rn(xv[2 * p]);
        __nv_bfloat16 h1 = __float2bfloat16_rn(xv[2 * p + 1]);
        __nv_bfloat16 l0 = __float2bfloat16_rn(xv[2 * p] - __bfloat162float(h0));
        __nv_bfloat16 l1 = __float2bfloat16_rn(xv[2 * p + 1] - __bfloat162float(h1));
        hp[p] = pack_bf2(h0, h1);
        lp[p] = pack_bf2(l0, l1);
    }
    size_t base = (size_t)n * 256 + c;
    *(uint2*)&g_Xh[base]       = make_uint2(hp[0], hp[1]);
    *(uint2*)&g_Xh[base + 128] = make_uint2(hp[2], hp[3]);
    *(uint2*)&g_Xl[base]       = make_uint2(lp[0], lp[1]);
    *(uint2*)&g_Xl[base + 128] = make_uint2(lp[2], lp[3]);
}

// ---------------- K4: tensor-core GEMM, bf16x3 split, cp.async 2-stage ------
#define GPITCH 40
#define GSTAGE 20480
#define GARR   5120

__global__ void __launch_bounds__(256, 2) k_gemm_tc(const float* __restrict__ bn,
                                                    const float* __restrict__ be,
                                                    float* __restrict__ out) {
    extern __shared__ __nv_bfloat16 smem[];
    int tid = threadIdx.x;
    int lane = tid & 31, wid = tid >> 5;
    int g = lane >> 2, t = lane & 3;
    int mw = (wid >> 1) * 32, nw = (wid & 1) * 64;
    int rowbase = blockIdx.x * 128;

    float acc[2][8][4];
#pragma unroll
    for (int mt = 0; mt < 2; mt++)
#pragma unroll
        for (int nt = 0; nt < 8; nt++)
#pragma unroll
            for (int p = 0; p < 4; p++) acc[mt][nt][p] = 0.f;

    auto issue = [&](int kc, int s) {
        __nv_bfloat16* Sxh = smem + s * GSTAGE;
        __nv_bfloat16* Sxl = Sxh + GARR;
        __nv_bfloat16* Swh = Sxl + GARR;
        __nv_bfloat16* Swl = Swh + GARR;
#pragma unroll
        for (int tt = 0; tt < 2; tt++) {
            int cc = tid + tt * 256;
            int row = cc >> 2, c16 = cc & 3;
            size_t gx = (size_t)(rowbase + row) * 256 + kc + c16 * 8;
            bool inb = (rowbase + row) < NN;
            cp16(&Sxh[row * GPITCH + c16 * 8], &g_Xh[gx], inb);
            cp16(&Sxl[row * GPITCH + c16 * 8], &g_Xl[gx], inb);
            size_t gw = (size_t)row * 256 + kc + c16 * 8;
            cp16(&Swh[row * GPITCH + c16 * 8], &g_Wh[gw], true);
            cp16(&Swl[row * GPITCH + c16 * 8], &g_Wl[gw], true);
        }
    };

    issue(0, 0);
    cp_commit();

    for (int it = 0; it < 8; it++) {
        if (it < 7) {
            issue((it + 1) * 32, (it + 1) & 1);
            cp_commit();
            cp_wait<1>();
        } else {
            cp_wait<0>();
        }
        __syncthreads();

        const __nv_bfloat16* Sxh = smem + (it & 1) * GSTAGE;
        const __nv_bfloat16* Sxl = Sxh + GARR;
        const __nv_bfloat16* Swh = Sxl + GARR;
        const __nv_bfloat16* Swl = Swh + GARR;

#pragma unroll
        for (int kk = 0; kk < 32; kk += 16) {
            unsigned ah[2][4], al[2][4];
#pragma unroll
            for (int mt = 0; mt < 2; mt++) {
                int rb = mw + mt * 16;
                ah[mt][0] = *(const unsigned*)&Sxh[(rb + g) * GPITCH + kk + t * 2];
                ah[mt][1] = *(const unsigned*)&Sxh[(rb + g + 8) * GPITCH + kk + t * 2];
                ah[mt][2] = *(const unsigned*)&Sxh[(rb + g) * GPITCH + kk + t * 2 + 8];
                ah[mt][3] = *(const unsigned*)&Sxh[(rb + g + 8) * GPITCH + kk + t * 2 + 8];
                al[mt][0] = *(const unsigned*)&Sxl[(rb + g) * GPITCH + kk + t * 2];
                al[mt][1] = *(const unsigned*)&Sxl[(rb + g + 8) * GPITCH + kk + t * 2];
                al[mt][2] = *(const unsigned*)&Sxl[(rb + g) * GPITCH + kk + t * 2 + 8];
                al[mt][3] = *(const unsigned*)&Sxl[(rb + g + 8) * GPITCH + kk + t * 2 + 8];
            }
#pragma unroll
            for (int nt = 0; nt < 8; nt++) {
                int nb = nw + nt * 8;
                unsigned bh0 = *(const unsigned*)&Swh[(nb + g) * GPITCH + kk + t * 2];
                unsigned bh1 = *(const unsigned*)&Swh[(nb + g) * GPITCH + kk + t * 2 + 8];
                unsigned bl0 = *(const unsigned*)&Swl[(nb + g) * GPITCH + kk + t * 2];
                unsigned bl1 = *(const unsigned*)&Swl[(nb + g) * GPITCH + kk + t * 2 + 8];
#pragma unroll
                for (int mt = 0; mt < 2; mt++) {
                    mma_bf16(acc[mt][nt], ah[mt][0], ah[mt][1], ah[mt][2], ah[mt][3], bh0, bh1);
                    mma_bf16(acc[mt][nt], ah[mt][0], ah[mt][1], ah[mt][2], ah[mt][3], bl0, bl1);
                    mma_bf16(acc[mt][nt], al[mt][0], al[mt][1], al[mt][2], al[mt][3], bh0, bh1);
                }
            }
        }
        __syncthreads();
    }

    // epilogue: bias + deg-gated edge bias
#pragma unroll
    for (int nt = 0; nt < 8; nt++) {
        int col = nw + nt * 8 + t * 2;
        float bn0 = __ldg(&bn[col]), bn1 = __ldg(&bn[col + 1]);
        float be0 = __ldg(&be[col]), be1 = __ldg(&be[col + 1]);
#pragma unroll
        for (int mt = 0; mt < 2; mt++) {
            int m0 = rowbase + mw + mt * 16 + g;
            if (m0 < NN) {
                float f = (g_deg[m0] > 0) ? 1.f : 0.f;
                __stcs((float2*)&out[(size_t)m0 * DD + col],
                       make_float2(acc[mt][nt][0] + bn0 + f * be0,
                                   acc[mt][nt][1] + bn1 + f * be1));
            }
            int m1 = m0 + 8;
            if (m1 < NN) {
                float f = (g_deg[m1] > 0) ? 1.f : 0.f;
                __stcs((float2*)&out[(size_t)m1 * DD + col],
                       make_float2(acc[mt][nt][2] + bn0 + f * be0,
                                   acc[mt][nt][3] + bn1 + f * be1));
            }
        }
    }

    // re-zero this CTA's g_deg rows for the next graph replay
    __syncthreads();
    if (tid < 128) {
        int m = rowbase + tid;
        if (m < NN) g_deg[m] = 0;
    }
}

// ---------------- launch ----------------------------------------------------
extern "C" void kernel_launch(void* const* d_in, const int* in_sizes, int n_in,
                              void* d_out, int out_size) {
    const float* nfeat = (const float*)d_in[0];
    const float* efeat = (const float*)d_in[1];
    const float* ew    = (const float*)d_in[2];
    const float* Wn    = (const float*)d_in[3];
    const float* bn    = (const float*)d_in[4];
    const float* We    = (const float*)d_in[5];
    const float* be    = (const float*)d_in[6];
    const int*   src   = (const int*)d_in[7];
    const int*   dst   = (const int*)d_in[8];
    float* out = (float*)d_out;

    const int gemm_smem = 2 * 4 * 128 * GPITCH * (int)sizeof(__nv_bfloat16);  // 81920
    cudaFuncSetAttribute(k_gemm_tc, cudaFuncAttributeMaxDynamicSharedMemorySize, gemm_smem);

    k_deg<<<800, 256>>>(dst, Wn, We);                       // #0
    k_scan<<<NSCAN, 1024>>>();                              // #1
    k_fill<<<(NE / 4 + 255) / 256, 256>>>(dst, src, ew);    // #2
    k_agg<<<(NN * 32 + 255) / 256, 256>>>(nfeat, efeat);    // #3 (profiled slot)
    k_gemm_tc<<<(NN + 127) / 128, 256, gemm_smem>>>(bn, be, out);  // #4
}